// round 5
// baseline (speedup 1.0000x reference)
#include <cuda_runtime.h>

// CrossEntropyLossWithGaussianSmoothedLabels
// pred: (32, 2048, 722) fp32, target: (32, 2048) int32 -> scalar mean loss.
//
// loss(row) = W * log(sum_c exp(pred[c])) - sum_k w_k * pred[base+k]
// where the w_k replicate the reference's clipped scatter-overwrite semantics.

#define NUM_CLASSES 722
#define HALF_CLASSES 361   // 722/2 float2 per row
#define WARPS_PER_BLOCK 8

__device__ __forceinline__ float warp_sum(float v) {
#pragma unroll
    for (int o = 16; o > 0; o >>= 1)
        v += __shfl_down_sync(0xffffffffu, v, o);
    return v;
}

__global__ void init_out_kernel(float* out) { out[0] = 0.0f; }

__global__ __launch_bounds__(WARPS_PER_BLOCK * 32)
void ce_smoothed_kernel(const float* __restrict__ pred,
                        const int* __restrict__ target,
                        float* __restrict__ out,
                        int n_rows) {
    __shared__ float blk_acc;
    const int tid  = threadIdx.x;
    const int warp = tid >> 5;
    const int lane = tid & 31;

    if (tid == 0) blk_acc = 0.0f;
    __syncthreads();

    const int row = blockIdx.x * WARPS_PER_BLOCK + warp;
    if (row < n_rows) {
        const float* prow = pred + (size_t)row * NUM_CLASSES;
        const float2* p2 = reinterpret_cast<const float2*>(prow);

        // ---- streaming exp-sum over the row (coalesced float2, read-once) ----
        float s = 0.0f;
#pragma unroll 8
        for (int j = lane; j < HALF_CLASSES; j += 32) {
            float2 v = __ldg(&p2[j]);
            s += __expf(v.x) + __expf(v.y);
        }
        s = warp_sum(s);   // valid in lane 0

        // ---- smoothed-label window: final weight after clipped overwrites ----
        // Reference write order (chronological): +3,-3,+2,-2,+1,-1,0,0, then t=1.0
        // Reverse-chronological check gives the surviving weight per index.
        const int t = target[row];
        float w = 0.0f, wp = 0.0f;
        if (lane < 7) {
            const int base = max(0, t - 3);
            const int idx  = base + lane;
            if (idx < NUM_CLASSES) {
                const float D1 = 0.60653065971263342360f;  // exp(-0.5)
                const float D2 = 0.36787944117144232160f;  // exp(-1)
                const float D3 = 0.13533528323661269189f;  // exp(-2)
                if      (idx == t)                          w = 1.0f;
                else if (idx == max(t - 1, 0))              w = D1;
                else if (idx == min(t + 1, NUM_CLASSES-1))  w = D1;
                else if (idx == max(t - 2, 0))              w = D2;
                else if (idx == min(t + 2, NUM_CLASSES-1))  w = D2;
                else if (idx == max(t - 3, 0))              w = D3;
                else if (idx == min(t + 3, NUM_CLASSES-1))  w = D3;
                if (w != 0.0f) wp = w * prow[idx];  // L1/L2 hit (row just streamed)
            }
        }
        const float W  = warp_sum(w);
        const float WP = warp_sum(wp);

        if (lane == 0) {
            const float loss = W * __logf(s) - WP;
            atomicAdd(&blk_acc, loss);
        }
    }
    __syncthreads();
    if (tid == 0) {
        atomicAdd(out, blk_acc * (1.0f / (float)n_rows));
    }
}

extern "C" void kernel_launch(void* const* d_in, const int* in_sizes, int n_in,
                              void* d_out, int out_size) {
    const float* pred   = (const float*)d_in[0];
    const int*   target = (const int*)d_in[1];
    float*       out    = (float*)d_out;

    const int n_rows = in_sizes[1];  // 32*2048 = 65536

    init_out_kernel<<<1, 1>>>(out);

    const int threads = WARPS_PER_BLOCK * 32;
    const int blocks  = (n_rows + WARPS_PER_BLOCK - 1) / WARPS_PER_BLOCK;
    ce_smoothed_kernel<<<blocks, threads>>>(pred, target, out, n_rows);
}